// round 10
// baseline (speedup 1.0000x reference)
#include <cuda_runtime.h>
#include <cuda_fp16.h>
#include <cstdint>

#define TT 1024
#define HH 50
#define PP 16
#define RH 72   // ring row stride in halfs

__device__ __forceinline__ float tanh_hw(float v) {
    float r; asm("tanh.approx.f32 %0, %1;" : "=f"(r) : "f"(v)); return r;
}
__device__ __forceinline__ __half2 as_h2(unsigned u) {
    return *reinterpret_cast<const __half2*>(&u);
}
// named barrier over one batch's 2 warps (64 threads)
__device__ __forceinline__ void bar_pair(int id) {
    asm volatile("bar.sync %0, %1;" :: "r"(id), "r"(64) : "memory");
}

__global__ __launch_bounds__(128, 4)
void lstm_fused_kernel(const float* __restrict__ x,
                       const float* __restrict__ params,
                       const float* __restrict__ W_ih,
                       const float* __restrict__ W_hh,
                       const float* __restrict__ b_ih,
                       const float* __restrict__ b_hh,
                       const float* __restrict__ W_lin,
                       const float* __restrict__ b_lin,
                       float* __restrict__ out)
{
    __shared__ __align__(16) float  xs[2][TT];        // both batches' input rows
    __shared__ __align__(16) __half ring[2][32][RH];  // per-batch fp16 h ring
    __shared__ __align__(16) float  wlin[68];

    const int tid  = threadIdx.x;                     // 0..127
    const int pair = tid >> 6;                        // batch within CTA (0/1)
    const int u    = tid & 63;                        // unit index 0..63 (>=50 pads)
    const int jj   = min(u, HH - 1);
    const int b    = blockIdx.x * 2 + pair;           // global batch
    const int barid = pair + 1;                       // named barrier id (0 reserved)

    // ---- init: stage both x rows, wlin, zero h[-1] ----
    {
        #pragma unroll
        for (int i = tid; i < 512; i += 128) {        // 2 rows x 256 float4
            const int row = i >> 8, idx = i & 255;
            const float4* xr = reinterpret_cast<const float4*>(
                x + (size_t)(blockIdx.x * 2 + row) * TT);
            reinterpret_cast<float4*>(xs[row])[idx] = xr[idx];
        }
        if (u < HH) ring[pair][31][u] = __float2half_rn(0.0f);
        if (tid < 68) wlin[tid] = (tid < HH + PP) ? W_lin[tid] : 0.0f;
    }
    const float blin = b_lin[0];

    // ---- per-thread: all 4 gate rows (i,f,g,o) for unit jj ----
    __half2 w[4][25];
    float wih[4], bias[4];
    #pragma unroll
    for (int k = 0; k < 4; ++k) {
        const int r = k * HH + jj;
        wih[k]  = W_ih[r];
        bias[k] = b_ih[r] + b_hh[r];
        const float2* wr = reinterpret_cast<const float2*>(W_hh + r * HH);
        #pragma unroll
        for (int q = 0; q < 25; ++q) { float2 v = wr[q]; w[k][q] = __floats2half2_rn(v.x, v.y); }
    }
    __syncthreads();                                  // init done (all 128)

    // ---- phase stagger: desynchronize co-resident CTAs (output-invariant) ----
    // Co-resident CTAs share bid % 148 -> distinct phases 0..3. Dependent-FMA
    // spin of ~340 cyc per phase so the 4 domains' tails interleave instead of
    // hitting the fma pipe idle all at once.
    {
        const int phase = (blockIdx.x / 148) & 3;
        float d = 1.0f;
        #pragma unroll 1
        for (int i = 0; i < phase * 36; ++i)
            asm volatile("fma.rn.f32 %0, %0, %1, %2;"
                         : "+f"(d) : "f"(0.9999999f), "f"(1e-7f));
    }

    float c = 0.0f;

    #pragma unroll 1
    for (int t = 0; t < TT; ++t) {
        const int cur  = t & 31;
        const int prev = (t + 31) & 31;

        // h[t-1]: 6 LDS.128 + 1 LDS.32, full-broadcast within the pair
        uint4 hv[6];
        const uint4* rp = reinterpret_cast<const uint4*>(&ring[pair][prev][0]);
        #pragma unroll
        for (int q = 0; q < 6; ++q) hv[q] = rp[q];
        const unsigned htail = reinterpret_cast<const unsigned*>(&ring[pair][prev][0])[24];
        const float xv = xs[pair][t];

        float raw[4];
        #pragma unroll
        for (int k = 0; k < 4; ++k) {
            __half2 a0 = __floats2half2_rn(0.f, 0.f), a1 = a0;
            #pragma unroll
            for (int q = 0; q < 6; ++q) {
                a0 = __hfma2(w[k][4 * q + 0], as_h2(hv[q].x), a0);
                a1 = __hfma2(w[k][4 * q + 1], as_h2(hv[q].y), a1);
                a0 = __hfma2(w[k][4 * q + 2], as_h2(hv[q].z), a0);
                a1 = __hfma2(w[k][4 * q + 3], as_h2(hv[q].w), a1);
            }
            a0 = __hfma2(w[k][24], as_h2(htail), a0);
            const __half2 s = __hadd2(a0, a1);
            raw[k] = fmaf(xv, wih[k], bias[k]) + __low2float(s) + __high2float(s);
        }

        const float vi = fmaf(0.5f, tanh_hw(0.5f * raw[0]), 0.5f);
        const float vf = fmaf(0.5f, tanh_hw(0.5f * raw[1]), 0.5f);
        const float vg = tanh_hw(raw[2]);
        const float vo = fmaf(0.5f, tanh_hw(0.5f * raw[3]), 0.5f);

        c = fmaf(vf, c, vi * vg);
        const float h = vo * tanh_hw(c);
        if (u < HH) ring[pair][cur][u] = __float2half_rn(h);

        bar_pair(barid);                              // h[cur] visible within the pair

        // ---- bulk output flush every 32 steps: first warp of the pair ----
        if ((t & 31) == 31) {
            if ((tid & 32) == 0) {
                const int lane = tid & 31;
                const int tg = t - 31 + lane;
                const __half* hr = ring[pair][lane];
                float s = blin;
                #pragma unroll
                for (int q = 0; q < 6; ++q) {
                    uint4 v = reinterpret_cast<const uint4*>(hr)[q];
                    float2 f0 = __half22float2(as_h2(v.x));
                    float2 f1 = __half22float2(as_h2(v.y));
                    float2 f2 = __half22float2(as_h2(v.z));
                    float2 f3 = __half22float2(as_h2(v.w));
                    s = fmaf(f0.x, wlin[8 * q + 0], s); s = fmaf(f0.y, wlin[8 * q + 1], s);
                    s = fmaf(f1.x, wlin[8 * q + 2], s); s = fmaf(f1.y, wlin[8 * q + 3], s);
                    s = fmaf(f2.x, wlin[8 * q + 4], s); s = fmaf(f2.y, wlin[8 * q + 5], s);
                    s = fmaf(f3.x, wlin[8 * q + 6], s); s = fmaf(f3.y, wlin[8 * q + 7], s);
                }
                {
                    float2 ft = __half22float2(as_h2(reinterpret_cast<const unsigned*>(hr)[24]));
                    s = fmaf(ft.x, wlin[48], s); s = fmaf(ft.y, wlin[49], s);
                }
                const float4* p4 = reinterpret_cast<const float4*>(
                    params + ((size_t)b * TT + tg) * PP);
                #pragma unroll
                for (int q = 0; q < 4; ++q) {
                    float4 p = __ldg(p4 + q);
                    s = fmaf(p.x, wlin[HH + 4 * q + 0], s);
                    s = fmaf(p.y, wlin[HH + 4 * q + 1], s);
                    s = fmaf(p.z, wlin[HH + 4 * q + 2], s);
                    s = fmaf(p.w, wlin[HH + 4 * q + 3], s);
                }
                out[(size_t)b * TT + tg] = s;
            }
            bar_pair(barid);                          // flush reads done before slot reuse
        }
    }
}

extern "C" void kernel_launch(void* const* d_in, const int* in_sizes, int n_in,
                              void* d_out, int out_size)
{
    const float* x      = (const float*)d_in[0];
    const float* params = (const float*)d_in[1];
    const float* W_ih   = (const float*)d_in[2];
    const float* W_hh   = (const float*)d_in[3];
    const float* b_ih   = (const float*)d_in[4];
    const float* b_hh   = (const float*)d_in[5];
    const float* W_lin  = (const float*)d_in[6];
    const float* b_lin  = (const float*)d_in[7];
    float* out = (float*)d_out;

    const int B = in_sizes[0] / TT;                   // 1024
    lstm_fused_kernel<<<B / 2, 128>>>(x, params, W_ih, W_hh, b_ih, b_hh,
                                      W_lin, b_lin, out);
}

// round 11
// speedup vs baseline: 1.0094x; 1.0094x over previous
#include <cuda_runtime.h>
#include <cuda_fp16.h>
#include <cstdint>

#define TT 1024
#define HH 50
#define PP 16
#define RH 72   // ring row stride in halfs

__device__ __forceinline__ float tanh_hw(float v) {
    float r; asm("tanh.approx.f32 %0, %1;" : "=f"(r) : "f"(v)); return r;
}
__device__ __forceinline__ unsigned h2u(__half2 h) { return *reinterpret_cast<unsigned*>(&h); }
__device__ __forceinline__ __half2 u2h(unsigned u) { return *reinterpret_cast<__half2*>(&u); }
__device__ __forceinline__ __half2 tanh_h2(__half2 v) {
    unsigned r; asm("tanh.approx.f16x2 %0, %1;" : "=r"(r) : "r"(h2u(v))); return u2h(r);
}
__device__ __forceinline__ unsigned prmt(unsigned a, unsigned b, unsigned sel) {
    unsigned d; asm("prmt.b32 %0, %1, %2, %3;" : "=r"(d) : "r"(a), "r"(b), "r"(sel)); return d;
}
__device__ __forceinline__ void bar_pair(int id) {
    asm volatile("bar.sync %0, %1;" :: "r"(id), "r"(64) : "memory");
}
__device__ __forceinline__ void cp_async16(uint32_t dst, const void* src) {
    asm volatile("cp.async.ca.shared.global [%0], [%1], 16;" :: "r"(dst), "l"(src) : "memory");
}

__global__ __launch_bounds__(128, 4)
void lstm_fused_kernel(const float* __restrict__ x,
                       const float* __restrict__ params,
                       const float* __restrict__ W_ih,
                       const float* __restrict__ W_hh,
                       const float* __restrict__ b_ih,
                       const float* __restrict__ b_hh,
                       const float* __restrict__ W_lin,
                       const float* __restrict__ b_lin,
                       float* __restrict__ out)
{
    __shared__ __align__(16) __half2 xs2h[2][TT];     // (x,x) per batch per step
    __shared__ __align__(16) __half  ring[2][32][RH]; // per-batch fp16 h ring
    __shared__ __align__(16) float   psm[2][32][PP];  // prefetched params window
    __shared__ __align__(16) float   wlin[68];

    const int tid  = threadIdx.x;                     // 0..127
    const int pair = tid >> 6;                        // batch within CTA (0/1)
    const int u    = tid & 63;                        // unit index (>=50 pads)
    const int jj   = min(u, HH - 1);
    const int b    = blockIdx.x * 2 + pair;
    const int barid = pair + 1;

    // ---- init ----
    {
        for (int i = tid; i < 2 * TT; i += 128) {     // x rows -> broadcast half2
            const int p = i >> 10, ti = i & (TT - 1);
            const float xv = x[(size_t)(blockIdx.x * 2 + p) * TT + ti];
            xs2h[p][ti] = __half2half2(__float2half_rn(xv));
        }
        if (u < HH) ring[pair][31][u] = __float2half_rn(0.0f);
        if (tid < 68) wlin[tid] = (tid < HH + PP) ? W_lin[tid] : 0.0f;
    }
    const float blin = b_lin[0];

    // ---- per-thread weights: gates i,f,g,o for unit jj; 0.5 pre-scale folded
    // into i,f,o rows (sigmoid(z) = 0.5*tanh(0.5z)+0.5) ----
    __half2 w[4][25];
    __half2 wx_if, wb_if, wx_go, wb_go;
    {
        float wihv[4], biasv[4];
        #pragma unroll
        for (int k = 0; k < 4; ++k) {
            const int r = k * HH + jj;
            const float sc = (k == 2) ? 1.0f : 0.5f;
            wihv[k]  = sc * W_ih[r];
            biasv[k] = sc * (b_ih[r] + b_hh[r]);
            const float2* wr = reinterpret_cast<const float2*>(W_hh + r * HH);
            #pragma unroll
            for (int q = 0; q < 25; ++q) {
                float2 v = wr[q];
                w[k][q] = __floats2half2_rn(sc * v.x, sc * v.y);
            }
        }
        wx_if = __floats2half2_rn(wihv[0], wihv[1]);
        wb_if = __floats2half2_rn(biasv[0], biasv[1]);
        wx_go = __floats2half2_rn(wihv[2], wihv[3]);
        wb_go = __floats2half2_rn(biasv[2], biasv[3]);
    }
    const __half2 H55   = __floats2half2_rn(0.5f, 0.5f);
    const __half2 Hm_go = __floats2half2_rn(1.0f, 0.5f);   // g: x1, o: x0.5
    const __half2 Ha_go = __floats2half2_rn(0.0f, 0.5f);   // g: +0, o: +0.5
    __syncthreads();

    float c = 0.0f;

    #pragma unroll 1
    for (int t = 0; t < TT; ++t) {
        const int cur  = t & 31;
        const int prev = (t + 31) & 31;

        // ---- params prefetch for window [t, t+31] (own batch) ----
        if ((t & 31) == 0) {
            #pragma unroll
            for (int c2 = 0; c2 < 2; ++c2) {
                const int cc   = u + 64 * c2;         // 0..127
                const int slot = cc >> 2, seg = cc & 3;
                const float* src = params + ((size_t)b * TT + (t + slot)) * PP + seg * 4;
                const uint32_t dst = (uint32_t)__cvta_generic_to_shared(&psm[pair][slot][seg * 4]);
                cp_async16(dst, src);
            }
            asm volatile("cp.async.commit_group;" ::: "memory");
        }

        // ---- h[t-1]: 6 LDS.128 + 1 LDS.32, broadcast ----
        uint4 hv[6];
        const uint4* rp = reinterpret_cast<const uint4*>(&ring[pair][prev][0]);
        #pragma unroll
        for (int q = 0; q < 6; ++q) hv[q] = rp[q];
        const unsigned htail = reinterpret_cast<const unsigned*>(&ring[pair][prev][0])[24];

        // ---- 4 gate dots (fp16 chains) ----
        __half2 a0[4], a1[4];
        #pragma unroll
        for (int k = 0; k < 4; ++k) { a0[k] = __floats2half2_rn(0.f, 0.f); a1[k] = a0[k]; }
        #pragma unroll
        for (int q = 0; q < 6; ++q) {
            #pragma unroll
            for (int k = 0; k < 4; ++k) {
                a0[k] = __hfma2(w[k][4 * q + 0], u2h(hv[q].x), a0[k]);
                a1[k] = __hfma2(w[k][4 * q + 1], u2h(hv[q].y), a1[k]);
                a0[k] = __hfma2(w[k][4 * q + 2], u2h(hv[q].z), a0[k]);
                a1[k] = __hfma2(w[k][4 * q + 3], u2h(hv[q].w), a1[k]);
            }
        }
        #pragma unroll
        for (int k = 0; k < 4; ++k) a0[k] = __hfma2(w[k][24], u2h(htail), a0[k]);

        const __half2 si = __hadd2(a0[0], a1[0]);
        const __half2 sf = __hadd2(a0[1], a1[1]);
        const __half2 sg = __hadd2(a0[2], a1[2]);
        const __half2 so = __hadd2(a0[3], a1[3]);

        // ---- packed tail: merge + x-contribution + tanh.f16x2 ----
        const __half2 xx = xs2h[pair][t];
        const __half2 xg_if = __hfma2(xx, wx_if, wb_if);
        const __half2 xg_go = __hfma2(xx, wx_go, wb_go);
        const __half2 raw_if = __hadd2(
            __hadd2(u2h(prmt(h2u(si), h2u(sf), 0x5410)),
                    u2h(prmt(h2u(si), h2u(sf), 0x7632))), xg_if);
        const __half2 raw_go = __hadd2(
            __hadd2(u2h(prmt(h2u(sg), h2u(so), 0x5410)),
                    u2h(prmt(h2u(sg), h2u(so), 0x7632))), xg_go);

        const __half2 v_if = __hfma2(tanh_h2(raw_if), H55, H55);      // (sig_i, sig_f)
        const __half2 v_go = __hfma2(tanh_h2(raw_go), Hm_go, Ha_go);  // (tanh_g, sig_o)

        const __half2 m = __hmul2(v_if, v_go);        // lo = vi*vg
        const float ig = __low2float(m);
        const float vf = __high2float(v_if);
        const float vo = __high2float(v_go);

        c = fmaf(vf, c, ig);
        const float h = vo * tanh_hw(c);
        if (u < HH) ring[pair][cur][u] = __float2half_rn(h);

        if ((t & 31) == 31) {
            asm volatile("cp.async.wait_group 0;" ::: "memory");
            bar_pair(barid);                          // h writes + psm visible in pair

            // ---- split flush: 2 lanes per timestep ----
            {
                const int wtid = tid & 63;
                const int slot = ((wtid >> 5) << 4) + ((tid & 31) >> 1);
                const int odd  = tid & 1;
                const int tg   = t - 31 + slot;
                const __half* hr = ring[pair][slot];
                float s;
                if (!odd) {
                    s = blin;                         // h[0..31]
                    #pragma unroll
                    for (int q = 0; q < 4; ++q) {
                        uint4 v = reinterpret_cast<const uint4*>(hr)[q];
                        float2 f0 = __half22float2(u2h(v.x));
                        float2 f1 = __half22float2(u2h(v.y));
                        float2 f2 = __half22float2(u2h(v.z));
                        float2 f3 = __half22float2(u2h(v.w));
                        s = fmaf(f0.x, wlin[8*q+0], s); s = fmaf(f0.y, wlin[8*q+1], s);
                        s = fmaf(f1.x, wlin[8*q+2], s); s = fmaf(f1.y, wlin[8*q+3], s);
                        s = fmaf(f2.x, wlin[8*q+4], s); s = fmaf(f2.y, wlin[8*q+5], s);
                        s = fmaf(f3.x, wlin[8*q+6], s); s = fmaf(f3.y, wlin[8*q+7], s);
                    }
                } else {
                    s = 0.0f;                         // h[32..49] + params
                    #pragma unroll
                    for (int q = 4; q < 6; ++q) {
                        uint4 v = reinterpret_cast<const uint4*>(hr)[q];
                        float2 f0 = __half22float2(u2h(v.x));
                        float2 f1 = __half22float2(u2h(v.y));
                        float2 f2 = __half22float2(u2h(v.z));
                        float2 f3 = __half22float2(u2h(v.w));
                        s = fmaf(f0.x, wlin[8*q+0], s); s = fmaf(f0.y, wlin[8*q+1], s);
                        s = fmaf(f1.x, wlin[8*q+2], s); s = fmaf(f1.y, wlin[8*q+3], s);
                        s = fmaf(f2.x, wlin[8*q+4], s); s = fmaf(f2.y, wlin[8*q+5], s);
                        s = fmaf(f3.x, wlin[8*q+6], s); s = fmaf(f3.y, wlin[8*q+7], s);
                    }
                    {
                        float2 ft = __half22float2(u2h(reinterpret_cast<const unsigned*>(hr)[24]));
                        s = fmaf(ft.x, wlin[48], s); s = fmaf(ft.y, wlin[49], s);
                    }
                    const float4* p4 = reinterpret_cast<const float4*>(&psm[pair][slot][0]);
                    #pragma unroll
                    for (int q = 0; q < 4; ++q) {
                        float4 p = p4[q];
                        s = fmaf(p.x, wlin[HH + 4*q + 0], s);
                        s = fmaf(p.y, wlin[HH + 4*q + 1], s);
                        s = fmaf(p.z, wlin[HH + 4*q + 2], s);
                        s = fmaf(p.w, wlin[HH + 4*q + 3], s);
                    }
                }
                s += __shfl_down_sync(0xffffffffu, s, 1);
                if (!odd) out[(size_t)b * TT + tg] = s;
            }
            bar_pair(barid);                          // flush reads done before reuse
        } else {
            bar_pair(barid);                          // h[cur] visible within pair
        }
    }
}

extern "C" void kernel_launch(void* const* d_in, const int* in_sizes, int n_in,
                              void* d_out, int out_size)
{
    const float* x      = (const float*)d_in[0];
    const float* params = (const float*)d_in[1];
    const float* W_ih   = (const float*)d_in[2];
    const float* W_hh   = (const float*)d_in[3];
    const float* b_ih   = (const float*)d_in[4];
    const float* b_hh   = (const float*)d_in[5];
    const float* W_lin  = (const float*)d_in[6];
    const float* b_lin  = (const float*)d_in[7];
    float* out = (float*)d_out;

    const int B = in_sizes[0] / TT;                   // 1024
    lstm_fused_kernel<<<B / 2, 128>>>(x, params, W_ih, W_hh, b_ih, b_hh,
                                      W_lin, b_lin, out);
}